// round 2
// baseline (speedup 1.0000x reference)
#include <cuda_runtime.h>
#include <math.h>

// Problem constants
#define BATCH 32
#define CIN   256
#define HH    32
#define WW    32
#define HW    1024                  // 32*32
#define NTOT  32768                 // BATCH*HW
#define K9    2304                  // 9*256
#define K25   6400                  // 25*256
#define OFFCH 50

// ---------------- scratch (static device globals; no allocation) ------------
__device__ float g_SA[(size_t)K9  * NTOT];   // 302 MB  im2col(x) / im2col(out)
__device__ float g_SB[(size_t)K25 * NTOT];   // 839 MB  deform-sampled im2col
__device__ float g_out[(size_t)BATCH * 256 * HW];   // intermediate "out"
__device__ float g_offb[(size_t)BATCH * OFFCH * HW];
__device__ float g_w1r[256 * K9];
__device__ float g_wor[OFFCH * K9];
__device__ float g_w3r[256 * K25];
__device__ float g_w2r[256 * K9];
__device__ float g_bn[6 * 256];   // scale1,shift1,scale3,shift3,scale2,shift2

// ---------------- BN param prep --------------------------------------------
__global__ void prep_bn(const float* __restrict__ g1, const float* __restrict__ b1,
                        const float* __restrict__ m1, const float* __restrict__ v1,
                        const float* __restrict__ g3, const float* __restrict__ b3,
                        const float* __restrict__ m3, const float* __restrict__ v3,
                        const float* __restrict__ g2, const float* __restrict__ b2,
                        const float* __restrict__ m2, const float* __restrict__ v2) {
    int i = threadIdx.x;
    if (i >= 256) return;
    float s1 = g1[i] * rsqrtf(v1[i] + 1e-5f);
    g_bn[i]        = s1;
    g_bn[256 + i]  = b1[i] - m1[i] * s1;
    float s3 = g3[i] * rsqrtf(v3[i] + 1e-5f);
    g_bn[512 + i]  = s3;
    g_bn[768 + i]  = b3[i] - m3[i] * s3;
    float s2 = g2[i] * rsqrtf(v2[i] + 1e-5f);
    g_bn[1024 + i] = s2;
    g_bn[1280 + i] = b2[i] - m2[i] * s2;
}

// ---------------- weight reorder:  w[O][C][T] -> wr[O][T*C + ...] -----------
// wr[o][t*256 + c] = w[o][c][t]
__global__ void reorder_w(const float* __restrict__ w, float* __restrict__ wr,
                          int O, int T) {
    int idx = blockIdx.x * blockDim.x + threadIdx.x;
    int total = O * 256 * T;
    if (idx >= total) return;
    int t = idx % T;
    int c = (idx / T) % 256;
    int o = idx / (T * 256);
    wr[(size_t)o * (256 * T) + t * 256 + c] = w[idx];
}

// ---------------- im2col for 3x3 pad1 ---------------------------------------
// S[(t*256+c)][b*1024+p] = in[b][c][ho-1+i][wo-1+j]   (zero pad)
__global__ void im2col3(const float* __restrict__ in, float* __restrict__ S) {
    int idx = blockIdx.x * blockDim.x + threadIdx.x;   // < 32*9*1024
    if (idx >= BATCH * 9 * HW) return;
    int p = idx & 1023;
    int t = (idx >> 10) % 9;
    int b = idx / (9 * HW);
    int ho = p >> 5, wo = p & 31;
    int i = t / 3, j = t % 3;
    int y = ho - 1 + i;
    int x = wo - 1 + j;
    bool valid = ((unsigned)y < 32u) && ((unsigned)x < 32u);
    const float* src = in + (size_t)b * (256 * HW) + y * 32 + x;
    float* Sp = S + (size_t)(t * 256) * NTOT + b * HW + p;
    #pragma unroll 4
    for (int c = 0; c < 256; c++) {
        float v = valid ? src[(size_t)c * HW] : 0.f;
        Sp[(size_t)c * NTOT] = v;
    }
}

// ---------------- deformable bilinear sampler -------------------------------
// S[(k*256+c)][b*1024+p] = bilinear(x[b][c], py, px) with zero outside borders
__global__ void sampler(const float* __restrict__ x, const float* __restrict__ off,
                        float* __restrict__ S) {
    int idx = blockIdx.x * blockDim.x + threadIdx.x;   // < 32*25*1024
    if (idx >= BATCH * 25 * HW) return;
    int p = idx & 1023;
    int k = (idx >> 10) % 25;
    int b = idx / (25 * HW);
    int ho = p >> 5, wo = p & 31;
    int i = k / 5, j = k % 5;
    const float* ob = off + (size_t)b * (OFFCH * HW);
    float dy = ob[(2 * k) * HW + p];
    float dx = ob[(2 * k + 1) * HW + p];
    float py = (float)(ho - 2 + i) + dy;
    float px = (float)(wo - 2 + j) + dx;
    float y0f = floorf(py), x0f = floorf(px);
    float wy1 = py - y0f, wx1 = px - x0f;
    float wy0 = 1.f - wy1, wx0 = 1.f - wx1;
    int y0 = (int)y0f, x0 = (int)x0f;
    int y1 = y0 + 1, x1 = x0 + 1;
    bool vy0 = ((unsigned)y0 < 32u), vy1 = ((unsigned)y1 < 32u);
    bool vx0 = ((unsigned)x0 < 32u), vx1 = ((unsigned)x1 < 32u);
    float w00 = (vy0 && vx0) ? wy0 * wx0 : 0.f;
    float w01 = (vy0 && vx1) ? wy0 * wx1 : 0.f;
    float w10 = (vy1 && vx0) ? wy1 * wx0 : 0.f;
    float w11 = (vy1 && vx1) ? wy1 * wx1 : 0.f;
    int cy0 = min(max(y0, 0), 31), cy1 = min(max(y1, 0), 31);
    int cx0 = min(max(x0, 0), 31), cx1 = min(max(x1, 0), 31);
    int a00 = cy0 * 32 + cx0, a01 = cy0 * 32 + cx1;
    int a10 = cy1 * 32 + cx0, a11 = cy1 * 32 + cx1;
    const float* xb = x + (size_t)b * (256 * HW);
    float* Sp = S + (size_t)(k * 256) * NTOT + b * HW + p;
    #pragma unroll 4
    for (int c = 0; c < 256; c++) {
        const float* xc = xb + (size_t)c * HW;
        float s = w00 * xc[a00] + w01 * xc[a01] + w10 * xc[a10] + w11 * xc[a11];
        Sp[(size_t)c * NTOT] = s;
    }
}

// ---------------- SGEMM  out[M, 32768] = A[M,K] * B[K,32768] + epilogue -----
// modes: 0 conv1: relu(bn)->out  | 1 offset: +bias->off buffer
//        2 deform: relu(bn)+aux->out | 3 conv2: relu(bn+aux)->out
#define BM 128
#define BN 128
#define BK 16
__global__ __launch_bounds__(256, 1)
void gemm_kernel(const float* __restrict__ A, const float* __restrict__ B,
                 int M, int K, int mode,
                 const float* __restrict__ scale, const float* __restrict__ shift,
                 const float* __restrict__ aux, float* __restrict__ out) {
    __shared__ float As[BK][BM + 4];
    __shared__ float Bs[BK][BN + 4];

    int tid = threadIdx.x;
    int tx = tid & 15;         // N direction (8 cols each)
    int ty = tid >> 4;         // M direction (8 rows each)
    int m0 = blockIdx.y * BM;
    int n0 = blockIdx.x * BN;

    float acc[8][8];
    #pragma unroll
    for (int i = 0; i < 8; i++)
        #pragma unroll
        for (int j = 0; j < 8; j++) acc[i][j] = 0.f;

    int arow = tid >> 2;            // 0..63
    int acol = (tid & 3) * 4;       // 0,4,8,12
    int brow = tid >> 5;            // 0..7
    int bcol = (tid & 31) * 4;      // 0..124

    for (int k0 = 0; k0 < K; k0 += BK) {
        // load A tile (transposed into As[k][m]); guard rows >= M
        #pragma unroll
        for (int r = 0; r < 2; r++) {
            int m = m0 + arow + r * 64;
            float4 v = make_float4(0.f, 0.f, 0.f, 0.f);
            if (m < M) v = *(const float4*)&A[(size_t)m * K + k0 + acol];
            As[acol + 0][arow + r * 64] = v.x;
            As[acol + 1][arow + r * 64] = v.y;
            As[acol + 2][arow + r * 64] = v.z;
            As[acol + 3][arow + r * 64] = v.w;
        }
        // load B tile
        #pragma unroll
        for (int r = 0; r < 2; r++) {
            float4 v = *(const float4*)&B[(size_t)(k0 + brow + r * 8) * NTOT + n0 + bcol];
            *(float4*)&Bs[brow + r * 8][bcol] = v;
        }
        __syncthreads();

        #pragma unroll
        for (int kk = 0; kk < BK; kk++) {
            float a[8], bb[8];
            *(float4*)&a[0]  = *(float4*)&As[kk][ty * 8];
            *(float4*)&a[4]  = *(float4*)&As[kk][ty * 8 + 4];
            *(float4*)&bb[0] = *(float4*)&Bs[kk][tx * 8];
            *(float4*)&bb[4] = *(float4*)&Bs[kk][tx * 8 + 4];
            #pragma unroll
            for (int i = 0; i < 8; i++)
                #pragma unroll
                for (int j = 0; j < 8; j++)
                    acc[i][j] = fmaf(a[i], bb[j], acc[i][j]);
        }
        __syncthreads();
    }

    // epilogue — each 128-col tile stays within one batch image (1024 % 128 == 0)
    int colbase = n0 + tx * 8;
    int bimg = colbase >> 10;
    int pbase = colbase & 1023;
    #pragma unroll
    for (int i = 0; i < 8; i++) {
        int row = m0 + ty * 8 + i;
        if (row >= M) continue;
        if (mode == 1) {
            float bias = shift[row];
            size_t base = (size_t)bimg * (OFFCH * HW) + (size_t)row * HW + pbase;
            #pragma unroll
            for (int j = 0; j < 8; j++) out[base + j] = acc[i][j] + bias;
        } else {
            float sc = scale[row], sh = shift[row];
            size_t base = (size_t)bimg * (256 * HW) + (size_t)row * HW + pbase;
            #pragma unroll
            for (int j = 0; j < 8; j++) {
                float v = fmaf(acc[i][j], sc, sh);
                if (mode == 0) {
                    out[base + j] = fmaxf(v, 0.f);
                } else if (mode == 2) {
                    out[base + j] = fmaxf(v, 0.f) + aux[base + j];
                } else { // mode 3
                    out[base + j] = fmaxf(v + aux[base + j], 0.f);
                }
            }
        }
    }
}

// ---------------- launcher ---------------------------------------------------
extern "C" void kernel_launch(void* const* d_in, const int* in_sizes, int n_in,
                              void* d_out, int out_size) {
    const float* x     = (const float*)d_in[0];
    const float* w1    = (const float*)d_in[1];
    const float* w_off = (const float*)d_in[2];
    const float* b_off = (const float*)d_in[3];
    const float* w3    = (const float*)d_in[4];
    const float* w2    = (const float*)d_in[5];
    const float* g1 = (const float*)d_in[6],  *b1 = (const float*)d_in[7];
    const float* m1 = (const float*)d_in[8],  *v1 = (const float*)d_in[9];
    const float* g3 = (const float*)d_in[10], *b3 = (const float*)d_in[11];
    const float* m3 = (const float*)d_in[12], *v3 = (const float*)d_in[13];
    const float* g2 = (const float*)d_in[14], *b2 = (const float*)d_in[15];
    const float* m2 = (const float*)d_in[16], *v2 = (const float*)d_in[17];
    float* out = (float*)d_out;

    float *sa, *sb, *gout, *goff, *w1r, *wor, *w3r, *w2r, *bn;
    cudaGetSymbolAddress((void**)&sa,   g_SA);
    cudaGetSymbolAddress((void**)&sb,   g_SB);
    cudaGetSymbolAddress((void**)&gout, g_out);
    cudaGetSymbolAddress((void**)&goff, g_offb);
    cudaGetSymbolAddress((void**)&w1r,  g_w1r);
    cudaGetSymbolAddress((void**)&wor,  g_wor);
    cudaGetSymbolAddress((void**)&w3r,  g_w3r);
    cudaGetSymbolAddress((void**)&w2r,  g_w2r);
    cudaGetSymbolAddress((void**)&bn,   g_bn);

    prep_bn<<<1, 256>>>(g1, b1, m1, v1, g3, b3, m3, v3, g2, b2, m2, v2);

    reorder_w<<<(256 * 256 * 9 + 255) / 256, 256>>>(w1, w1r, 256, 9);
    reorder_w<<<(OFFCH * 256 * 9 + 255) / 256, 256>>>(w_off, wor, OFFCH, 9);
    reorder_w<<<(256 * 256 * 25 + 255) / 256, 256>>>(w3, w3r, 256, 25);
    reorder_w<<<(256 * 256 * 9 + 255) / 256, 256>>>(w2, w2r, 256, 9);

    // im2col(x) -> S_A
    im2col3<<<(BATCH * 9 * HW) / 256, 256>>>(x, sa);

    // conv1: relu(bn1(w1 * S_A)) -> g_out
    gemm_kernel<<<dim3(NTOT / BN, 2), 256>>>(w1r, sa, 256, K9, 0,
                                             bn + 0, bn + 256, nullptr, gout);
    // offset conv: w_off * S_A + b_off -> g_offb
    gemm_kernel<<<dim3(NTOT / BN, 1), 256>>>(wor, sa, OFFCH, K9, 1,
                                             nullptr, b_off, nullptr, goff);
    // deformable sampling -> S_B
    sampler<<<(BATCH * 25 * HW) / 256, 256>>>(x, goff, sb);

    // deform conv: g_out += relu(bn3(w3 * S_B))
    gemm_kernel<<<dim3(NTOT / BN, 2), 256>>>(w3r, sb, 256, K25, 2,
                                             bn + 512, bn + 768, gout, gout);

    // im2col(g_out) -> S_A (reuse)
    im2col3<<<(BATCH * 9 * HW) / 256, 256>>>(gout, sa);

    // conv2: relu(bn2(w2 * S_A) + x) -> d_out
    gemm_kernel<<<dim3(NTOT / BN, 2), 256>>>(w2r, sa, 256, K9, 3,
                                             bn + 1024, bn + 1280, x, out);
}